// round 4
// baseline (speedup 1.0000x reference)
#include <cuda_runtime.h>
#include <math.h>
#include <stdint.h>
#include <stddef.h>

// fixed problem shapes
#define BDIM 8
#define HDIM 8
#define DM 512
#define DA 256
#define DP 128
#define MDIM 32
#define DK 64
#define DAH 32
#define DPH 16
#define SDIM 6144

// ---------------- device scratch ----------------
__device__ float d_WqM[HDIM*DK*DM];
__device__ float d_WkM[HDIM*DK*DM];
__device__ float d_WvM[HDIM*DK*DM];
__device__ float d_WOM[DM*DM];
__device__ float d_Kn[(size_t)BDIM*HDIM*SDIM*DK];   // ~100 MB
__device__ float d_Qv[BDIM*HDIM*MDIM*DK];
__device__ float d_QA[BDIM*HDIM*DAH];
__device__ float d_QP[BDIM*HDIM*DPH];
__device__ float d_tn[BDIM*HDIM*SDIM];
__device__ float d_dot2[BDIM*HDIM*SDIM];
__device__ float d_dot3[BDIM*HDIM*SDIM];
__device__ float d_attn[BDIM*HDIM*SDIM];
__device__ float d_alast[BDIM*HDIM];
__device__ float d_xbar[BDIM*HDIM*DM];
__device__ float d_gi[BDIM*31*192];
__device__ float d_res[BDIM*DK];
__device__ float d_deta[BDIM*DM];

__device__ __forceinline__ void mma_tf32(float* c, const uint32_t* a, uint32_t b0, uint32_t b1) {
    asm volatile("mma.sync.aligned.m16n8k8.row.col.f32.tf32.tf32.f32 "
        "{%0,%1,%2,%3}, {%4,%5,%6,%7}, {%8,%9}, {%0,%1,%2,%3};\n"
        : "+f"(c[0]), "+f"(c[1]), "+f"(c[2]), "+f"(c[3])
        : "r"(a[0]), "r"(a[1]), "r"(a[2]), "r"(a[3]), "r"(b0), "r"(b1));
}

__device__ __forceinline__ void cpa16(uint32_t saddr, const void* g) {
    asm volatile("cp.async.cg.shared.global [%0], [%1], 16;" :: "r"(saddr), "l"(g));
}
__device__ __forceinline__ void cpa_commit() { asm volatile("cp.async.commit_group;"); }

// ---------------- masked weights + zero xbar ----------------
__global__ void mask_kernel(const float* __restrict__ Wq, const float* __restrict__ Wk,
                            const float* __restrict__ Wv, const float* __restrict__ WO,
                            const int* __restrict__ G) {
    int i = blockIdx.x*256 + threadIdx.x;
    const int NW = HDIM*DK*DM;
    if (i < NW) {
        int d = i & 511;
        int c = (i >> 9) & 63;
        float g = (float)G[c*64 + (d & 63)];
        d_WqM[i] = Wq[i]*g;
        d_WkM[i] = Wk[i]*g;
        d_WvM[i] = Wv[i]*g;
    }
    if (i < DM*DM) {
        int j = i & 511, r = i >> 9;
        d_WOM[i] = WO[i]*(float)G[(r & 63)*64 + (j & 63)];
    }
    if (i < BDIM*HDIM*DM) d_xbar[i] = 0.f;
}

// ---------------- Qv: last M rows, masked proj + l2norm (fp32, tiny) ----------------
__global__ void qv_kernel(const float* __restrict__ memory, const float* __restrict__ x_pre,
                          const float* __restrict__ bq, int S) {
    int m = blockIdx.x & 31, h = (blockIdx.x >> 5) & 7, b = blockIdx.x >> 8;
    __shared__ float xs[DM];
    __shared__ float wp[2];
    int s = S - MDIM + m;
    const float* row = (s < S-1) ? memory + ((size_t)b*(S-1) + s)*DM : x_pre + (size_t)b*DM;
    for (int i = threadIdx.x; i < DM; i += 64) xs[i] = row[i];
    __syncthreads();
    int c = threadIdx.x;
    const float* wr = d_WqM + ((size_t)h*DK + c)*DM;
    float acc = bq[h*DK + c];
    #pragma unroll 8
    for (int d = 0; d < DM; d++) acc += xs[d]*wr[d];
    float v = acc*acc;
    for (int o = 16; o; o >>= 1) v += __shfl_xor_sync(0xffffffffu, v, o);
    if ((c & 31) == 0) wp[c >> 5] = v;
    __syncthreads();
    float inv = 1.f / fmaxf(sqrtf(wp[0] + wp[1]), 1e-12f);
    d_Qv[(((size_t)b*HDIM + h)*MDIM + m)*DK + c] = acc*inv;
}

// ---------------- tensor-core projection (tf32 mma, cp.async double-buffered) ----------------
// MODE 0: kproj  (x = [memory; x_pre]; W = d_WkM; out = normalized rows -> d_Kn)
// MODE 1: aux    (epilogue: dot with d_QA -> d_dot2)
// MODE 2: pos    (epilogue: dot with d_QP -> d_dot3)
template<int DIN, int DOUT, int MODE, int BLOCKT, int NW_N>
__global__ void __launch_bounds__(BLOCKT)
proj_mma_kernel(const float* __restrict__ src0, const float* __restrict__ x_pre,
                const float* __restrict__ W, const float* __restrict__ bias,
                int S, int Wn) {
    constexpr int NWARP = BLOCKT/32;
    constexpr int NW_M = NWARP/NW_N;
    constexpr int TM   = NW_M*32;
    constexpr int WT_N = DOUT/NW_N;
    constexpr int NFN  = WT_N/8;
    constexpr int NCH  = DIN/32;

    __shared__ uint32_t Xs[2*TM*36];
    __shared__ uint32_t Wss[2*DOUT*36];
    __shared__ float bs_s[DOUT];
    __shared__ float qs_s[DOUT];
    __shared__ float red_s[TM*2];

    int tid = threadIdx.x;
    int lane = tid & 31, wid = tid >> 5;
    int g = lane >> 2, tig = lane & 3;
    int warp_n = wid % NW_N, warp_m = wid / NW_N;
    int rb = warp_m*32, cb = warp_n*WT_N;
    int s0 = blockIdx.x*TM, h = blockIdx.y, b = blockIdx.z;
    int bh = b*HDIM + h;

    uint32_t xB = (uint32_t)__cvta_generic_to_shared(Xs);
    uint32_t wB = (uint32_t)__cvta_generic_to_shared(Wss);

    for (int i = tid; i < DOUT; i += BLOCKT) {
        bs_s[i] = bias[h*DOUT + i];
        if (MODE == 1) qs_s[i] = d_QA[(size_t)bh*DAH + i];
        if (MODE == 2) qs_s[i] = d_QP[(size_t)bh*DPH + i];
    }

    auto load_chunk = [&](int ch, int buf) {
        int d0 = ch*32;
        #pragma unroll
        for (int it = 0; it < TM*8/BLOCKT; it++) {
            int e = it*BLOCKT + tid;
            int row = e >> 3, c4 = (e & 7)*4;
            int s = s0 + row;
            const float* rp;
            if (MODE == 0)
                rp = (s < S-1) ? src0 + ((size_t)b*(S-1) + s)*DIN : x_pre + (size_t)b*DIN;
            else
                rp = src0 + ((size_t)b*S + s)*DIN;
            cpa16(xB + (buf*TM*36 + row*36 + c4)*4, rp + d0 + c4);
        }
        for (int e = tid; e < DOUT*8; e += BLOCKT) {
            int rr = e >> 3, c4 = (e & 7)*4;
            const float* wp;
            if (MODE == 0) wp = d_WkM + ((size_t)(h*DOUT + rr))*DIN + d0 + c4;
            else           wp = W + ((size_t)(h*DOUT + rr))*DIN + d0 + c4;
            cpa16(wB + (buf*DOUT*36 + rr*36 + c4)*4, wp);
        }
    };

    float acc[2][NFN][4];
    #pragma unroll
    for (int mi = 0; mi < 2; mi++)
        #pragma unroll
        for (int ni = 0; ni < NFN; ni++)
            #pragma unroll
            for (int q = 0; q < 4; q++) acc[mi][ni][q] = 0.f;

    load_chunk(0, 0);
    cpa_commit();

    for (int ch = 0; ch < NCH; ch++) {
        if (ch + 1 < NCH) { load_chunk(ch+1, (ch+1) & 1); cpa_commit(); }
        if (ch + 1 < NCH) asm volatile("cp.async.wait_group 1;" ::: "memory");
        else              asm volatile("cp.async.wait_group 0;" ::: "memory");
        __syncthreads();
        const uint32_t* Xb = Xs + (ch & 1)*TM*36;
        const uint32_t* Wb = Wss + (ch & 1)*DOUT*36;
        #pragma unroll
        for (int ks = 0; ks < 4; ks++) {
            int k0 = ks*8;
            uint32_t a[2][4];
            #pragma unroll
            for (int mi = 0; mi < 2; mi++) {
                int r = rb + mi*16 + g;
                a[mi][0] = Xb[r*36 + k0 + tig];
                a[mi][1] = Xb[(r+8)*36 + k0 + tig];
                a[mi][2] = Xb[r*36 + k0 + tig + 4];
                a[mi][3] = Xb[(r+8)*36 + k0 + tig + 4];
            }
            #pragma unroll
            for (int ni = 0; ni < NFN; ni++) {
                int cn = cb + ni*8 + g;
                uint32_t b0 = Wb[cn*36 + k0 + tig];
                uint32_t b1 = Wb[cn*36 + k0 + tig + 4];
                #pragma unroll
                for (int mi = 0; mi < 2; mi++) mma_tf32(acc[mi][ni], a[mi], b0, b1);
            }
        }
        __syncthreads();
    }

    // ---- epilogue: bias + per-row l2 norm ----
    float sl[2] = {0.f, 0.f}, sh[2] = {0.f, 0.f};
    #pragma unroll
    for (int mi = 0; mi < 2; mi++)
        #pragma unroll
        for (int ni = 0; ni < NFN; ni++) {
            int c0 = cb + ni*8 + 2*tig, c1 = c0 + 1;
            acc[mi][ni][0] += bs_s[c0];
            acc[mi][ni][1] += bs_s[c1];
            acc[mi][ni][2] += bs_s[c0];
            acc[mi][ni][3] += bs_s[c1];
            sl[mi] += acc[mi][ni][0]*acc[mi][ni][0] + acc[mi][ni][1]*acc[mi][ni][1];
            sh[mi] += acc[mi][ni][2]*acc[mi][ni][2] + acc[mi][ni][3]*acc[mi][ni][3];
        }
    #pragma unroll
    for (int mi = 0; mi < 2; mi++) {
        sl[mi] += __shfl_xor_sync(0xffffffffu, sl[mi], 1);
        sl[mi] += __shfl_xor_sync(0xffffffffu, sl[mi], 2);
        sh[mi] += __shfl_xor_sync(0xffffffffu, sh[mi], 1);
        sh[mi] += __shfl_xor_sync(0xffffffffu, sh[mi], 2);
    }
    if (NW_N == 2) {
        if (tig == 0) {
            #pragma unroll
            for (int mi = 0; mi < 2; mi++) {
                int rl = rb + mi*16 + g;
                red_s[rl*2 + warp_n] = sl[mi];
                red_s[(rl+8)*2 + warp_n] = sh[mi];
            }
        }
        __syncthreads();
        #pragma unroll
        for (int mi = 0; mi < 2; mi++) {
            int rl = rb + mi*16 + g;
            sl[mi] = red_s[rl*2] + red_s[rl*2+1];
            sh[mi] = red_s[(rl+8)*2] + red_s[(rl+8)*2+1];
        }
    }
    float il[2], ih[2];
    #pragma unroll
    for (int mi = 0; mi < 2; mi++) {
        il[mi] = 1.f / fmaxf(sqrtf(sl[mi]), 1e-12f);
        ih[mi] = 1.f / fmaxf(sqrtf(sh[mi]), 1e-12f);
    }

    if (MODE == 0) {
        #pragma unroll
        for (int mi = 0; mi < 2; mi++) {
            int rl = rb + mi*16 + g;
            size_t base_l = ((size_t)bh*S + s0 + rl)*DK;
            size_t base_h = ((size_t)bh*S + s0 + rl + 8)*DK;
            #pragma unroll
            for (int ni = 0; ni < NFN; ni++) {
                int c0 = cb + ni*8 + 2*tig;
                float2 v0 = make_float2(acc[mi][ni][0]*il[mi], acc[mi][ni][1]*il[mi]);
                float2 v1 = make_float2(acc[mi][ni][2]*ih[mi], acc[mi][ni][3]*ih[mi]);
                *(float2*)&d_Kn[base_l + c0] = v0;
                *(float2*)&d_Kn[base_h + c0] = v1;
            }
        }
    } else {
        float* dst = (MODE == 1) ? d_dot2 : d_dot3;
        #pragma unroll
        for (int mi = 0; mi < 2; mi++) {
            float dl = 0.f, dh = 0.f;
            #pragma unroll
            for (int ni = 0; ni < NFN; ni++) {
                int c0 = cb + ni*8 + 2*tig, c1 = c0 + 1;
                dl += acc[mi][ni][0]*qs_s[c0] + acc[mi][ni][1]*qs_s[c1];
                dh += acc[mi][ni][2]*qs_s[c0] + acc[mi][ni][3]*qs_s[c1];
            }
            dl += __shfl_xor_sync(0xffffffffu, dl, 1);
            dl += __shfl_xor_sync(0xffffffffu, dl, 2);
            dh += __shfl_xor_sync(0xffffffffu, dh, 1);
            dh += __shfl_xor_sync(0xffffffffu, dh, 2);
            if (tig == 0) {
                int rl = rb + mi*16 + g;
                int wl = s0 + rl - 31;
                int wh = wl + 8;
                if (wl >= 0 && wl < Wn) dst[(size_t)bh*S + wl] = dl*il[mi];
                if (wh >= 0 && wh < Wn) dst[(size_t)bh*S + wh] = dh*ih[mi];
            }
        }
    }
}

// ---------------- banded Qv . Kn -> tn  (tf32 mma version) ----------------
// block: 128 threads, handles 64 w-positions; loads K rows s0..s0+95
__global__ void __launch_bounds__(128) band_mma_kernel(int S, int Wn) {
    __shared__ uint32_t Qs[32*68];
    __shared__ uint32_t Ks[96*68];
    __shared__ float Ps[32*100];
    int tid = threadIdx.x;
    int lane = tid & 31, wid = tid >> 5;
    int g = lane >> 2, tig = lane & 3;
    int w0 = blockIdx.x*64, h = blockIdx.y, b = blockIdx.z;
    int bh = b*HDIM + h;

    uint32_t qB = (uint32_t)__cvta_generic_to_shared(Qs);
    uint32_t kB = (uint32_t)__cvta_generic_to_shared(Ks);

    // stage K rows (96 x 64) and Q (32 x 64)
    for (int e = tid; e < 96*16; e += 128) {
        int r = e >> 4, c4 = (e & 15)*4;
        int s = w0 + r;
        uint32_t sa = kB + (r*68 + c4)*4;
        if (s < S) cpa16(sa, d_Kn + ((size_t)bh*S + s)*DK + c4);
        else {
            *(float4*)((char*)Ks + (size_t)(r*68 + c4)*4) = make_float4(0.f,0.f,0.f,0.f);
        }
    }
    for (int e = tid; e < 32*16; e += 128) {
        int r = e >> 4, c4 = (e & 15)*4;
        cpa16(qB + (r*68 + c4)*4, d_Qv + ((size_t)bh*MDIM + r)*DK + c4);
    }
    cpa_commit();
    asm volatile("cp.async.wait_group 0;" ::: "memory");
    __syncthreads();

    // P = Qv (32x64) @ K^T (64x96); warp wid covers n-range [wid*24, wid*24+24)
    float acc[2][3][4];
    #pragma unroll
    for (int mi = 0; mi < 2; mi++)
        #pragma unroll
        for (int ni = 0; ni < 3; ni++)
            #pragma unroll
            for (int q = 0; q < 4; q++) acc[mi][ni][q] = 0.f;
    int nb = wid*24;
    #pragma unroll
    for (int ks = 0; ks < 8; ks++) {
        int k0 = ks*8;
        uint32_t a[2][4];
        #pragma unroll
        for (int mi = 0; mi < 2; mi++) {
            int r = mi*16 + g;
            a[mi][0] = Qs[r*68 + k0 + tig];
            a[mi][1] = Qs[(r+8)*68 + k0 + tig];
            a[mi][2] = Qs[r*68 + k0 + tig + 4];
            a[mi][3] = Qs[(r+8)*68 + k0 + tig + 4];
        }
        #pragma unroll
        for (int ni = 0; ni < 3; ni++) {
            int cn = nb + ni*8 + g;
            uint32_t b0 = Ks[cn*68 + k0 + tig];
            uint32_t b1 = Ks[cn*68 + k0 + tig + 4];
            #pragma unroll
            for (int mi = 0; mi < 2; mi++) mma_tf32(acc[mi][ni], a[mi], b0, b1);
        }
    }
    // write P to smem
    #pragma unroll
    for (int mi = 0; mi < 2; mi++)
        #pragma unroll
        for (int ni = 0; ni < 3; ni++) {
            int c0 = nb + ni*8 + 2*tig;
            int r = mi*16 + g;
            Ps[r*100 + c0]     = acc[mi][ni][0];
            Ps[r*100 + c0 + 1] = acc[mi][ni][1];
            Ps[(r+8)*100 + c0]     = acc[mi][ni][2];
            Ps[(r+8)*100 + c0 + 1] = acc[mi][ni][3];
        }
    __syncthreads();
    // diagonal reduce: tn[w0+t] = mean_m P[m][t+m]
    if (tid < 64) {
        int w = w0 + tid;
        if (w < Wn) {
            float s = 0.f;
            #pragma unroll
            for (int m = 0; m < 32; m++) s += Ps[m*100 + tid + m];
            d_tn[(size_t)bh*S + w] = s*(1.f/32.f);
        }
    }
}

// ---------------- QA / QP (last-row queries, fp32) ----------------
__global__ void qa_kernel(const float* __restrict__ aux, const float* __restrict__ Wqa,
                          const float* __restrict__ bqa, int S) {
    int h = blockIdx.x & 7, b = blockIdx.x >> 3;
    int c = threadIdx.x;  // 32
    const float* ar = aux + ((size_t)b*S + (S-1))*DA;
    const float* wr = Wqa + ((size_t)h*DAH + c)*DA;
    float acc = bqa[h*DAH + c];
    #pragma unroll 4
    for (int d = 0; d < DA; d++) acc += ar[d]*wr[d];
    float v = acc*acc;
    for (int o = 16; o; o >>= 1) v += __shfl_xor_sync(0xffffffffu, v, o);
    float inv = 1.f / fmaxf(sqrtf(v), 1e-12f);
    d_QA[((size_t)b*HDIM + h)*DAH + c] = acc*inv;
}

__global__ void qp_kernel(const float* __restrict__ pos, const float* __restrict__ Wqp,
                          const float* __restrict__ bqp, int S) {
    int h = blockIdx.x & 7, b = blockIdx.x >> 3;
    int lane = threadIdx.x;   // 32
    int c = lane & 15;
    const float* pr = pos + ((size_t)b*S + (S-1))*DP;
    const float* wr = Wqp + ((size_t)h*DPH + c)*DP;
    float acc = bqp[h*DPH + c];
    #pragma unroll 4
    for (int d = 0; d < DP; d++) acc += pr[d]*wr[d];
    float v = acc*acc;
    for (int o = 8; o; o >>= 1) v += __shfl_xor_sync(0xffffffffu, v, o);
    float inv = 1.f / fmaxf(sqrtf(v), 1e-12f);
    if (lane < 16) d_QP[((size_t)b*HDIM + h)*DPH + c] = acc*inv;
}

// ---------------- softmax over Wn ----------------
__global__ void softmax_kernel(const float* __restrict__ w1, const float* __restrict__ w2,
                               const float* __restrict__ w3, int S, int Wn) {
    int bh = blockIdx.x, t = threadIdx.x;   // 256
    __shared__ float red[8];
    __shared__ float sval;
    float c1 = w1[0], c2 = w2[0], c3 = w3[0];
    size_t base = (size_t)bh*S;
    float mx = -1e30f;
    for (int i = t; i < Wn; i += 256) {
        float l = c1*d_tn[base+i] + c2*d_dot2[base+i] + c3*d_dot3[base+i];
        d_attn[base+i] = l;
        mx = fmaxf(mx, l);
    }
    for (int o = 16; o; o >>= 1) mx = fmaxf(mx, __shfl_xor_sync(0xffffffffu, mx, o));
    if ((t & 31) == 0) red[t >> 5] = mx;
    __syncthreads();
    if (t == 0) { float m = red[0]; for (int i = 1; i < 8; i++) m = fmaxf(m, red[i]); sval = m; }
    __syncthreads();
    float MX = sval, sum = 0.f;
    for (int i = t; i < Wn; i += 256) {
        float e = __expf(d_attn[base+i] - MX);
        d_attn[base+i] = e;
        sum += e;
    }
    for (int o = 16; o; o >>= 1) sum += __shfl_xor_sync(0xffffffffu, sum, o);
    __syncthreads();
    if ((t & 31) == 0) red[t >> 5] = sum;
    __syncthreads();
    if (t == 0) { float m = 0.f; for (int i = 0; i < 8; i++) m += red[i]; sval = m; }
    __syncthreads();
    float inv = 1.f / sval;
    for (int i = t; i < Wn; i += 256) {
        float a = d_attn[base+i]*inv;
        d_attn[base+i] = a;
        if (i == Wn-1) d_alast[bh] = a;
    }
}

// ---------------- xbar: attn-weighted row sums of x ----------------
__global__ void xbar_kernel(const float* __restrict__ memory, int S, int Wn) {
    __shared__ float a_s[8][64];
    int t = threadIdx.x;                 // 256
    int w0 = blockIdx.x*64, b = blockIdx.y;
    for (int i = t; i < 512; i += 256) {
        int hh = i >> 6, j = i & 63;
        int w = w0 + j;
        a_s[hh][j] = (w < Wn-1) ? d_attn[((size_t)b*HDIM + hh)*S + w] : 0.f;
    }
    __syncthreads();
    float acc[8][2];
    #pragma unroll
    for (int h = 0; h < 8; h++) { acc[h][0] = 0.f; acc[h][1] = 0.f; }
    int nrow = Wn - 1 - w0; if (nrow > 64) nrow = 64;
    for (int j = 0; j < nrow; j++) {
        size_t sr = (size_t)b*(S-1) + (31 + w0 + j);
        float x0 = memory[sr*DM + t];
        float x1 = memory[sr*DM + 256 + t];
        #pragma unroll
        for (int h = 0; h < 8; h++) {
            float a = a_s[h][j];
            acc[h][0] += a*x0;
            acc[h][1] += a*x1;
        }
    }
    #pragma unroll
    for (int h = 0; h < 8; h++) {
        atomicAdd(&d_xbar[((size_t)b*HDIM + h)*DM + t], acc[h][0]);
        atomicAdd(&d_xbar[((size_t)b*HDIM + h)*DM + 256 + t], acc[h][1]);
    }
}

// ---------------- GRU ----------------
__global__ void gi_kernel(const float* __restrict__ memory, const float* __restrict__ W_ih,
                          const float* __restrict__ b_ih, int S) {
    int tt = blockIdx.x, b = blockIdx.y;
    __shared__ float xs[DM];
    int s = S - MDIM + tt;               // always memory row (tt <= 30)
    const float* row = memory + ((size_t)b*(S-1) + s)*DM;
    for (int i = threadIdx.x; i < DM; i += 192) xs[i] = row[i];
    __syncthreads();
    int j = threadIdx.x;
    const float* wr = W_ih + (size_t)j*DM;
    float acc = b_ih[j];
    #pragma unroll 8
    for (int d = 0; d < DM; d++) acc += xs[d]*wr[d];
    d_gi[((size_t)b*31 + tt)*192 + j] = acc;
}

__global__ void gru_kernel(const float* __restrict__ W_hh, const float* __restrict__ b_hh) {
    int b = blockIdx.x, j = threadIdx.x;  // 192
    __shared__ float hs[DK];
    __shared__ float gh_s[192];
    if (j < DK) hs[j] = 0.f;
    __syncthreads();
    float bh = b_hh[j];
    const float* wr = W_hh + (size_t)j*DK;
    for (int t = 0; t < 31; t++) {
        float gh = bh;
        #pragma unroll 8
        for (int k2 = 0; k2 < DK; k2++) gh += hs[k2]*wr[k2];
        gh_s[j] = gh;
        __syncthreads();
        float hn = 0.f;
        if (j < DK) {
            const float* gi = d_gi + ((size_t)b*31 + t)*192;
            float r = 1.f/(1.f + __expf(-(gi[j] + gh_s[j])));
            float z = 1.f/(1.f + __expf(-(gi[64 + j] + gh_s[64 + j])));
            float n = tanhf(gi[128 + j] + r*gh_s[128 + j]);
            hn = (1.f - z)*n + z*hs[j];
        }
        __syncthreads();
        if (j < DK) hs[j] = hn;
        __syncthreads();
    }
    if (j < DK) d_res[b*DK + j] = hs[j];
}

// ---------------- deta = xbar @ WvM^T + bv*(1-alast) + alast*res ----------------
__global__ void deta_kernel(const float* __restrict__ bv) {
    int bh = blockIdx.x;
    int b = bh >> 3, h = bh & 7;
    int c = threadIdx.x;                 // 64
    __shared__ float xb[DM];
    for (int i = c; i < DM; i += 64) xb[i] = d_xbar[(size_t)bh*DM + i];
    __syncthreads();
    const float* wv = d_WvM + ((size_t)h*DK + c)*DM;
    float acc = 0.f;
    #pragma unroll 8
    for (int d = 0; d < DM; d++) acc += xb[d]*wv[d];
    float al = d_alast[bh];
    d_deta[(size_t)b*DM + h*DK + c] = acc + bv[h*DK + c]*(1.f - al) + al*d_res[b*DK + c];
}

// ---------------- out = x_pre + deta @ WOM^T + bO ----------------
__global__ void out_kernel(const float* __restrict__ x_pre, const float* __restrict__ bO,
                           float* __restrict__ out) {
    int b = blockIdx.x, j = threadIdx.x;  // 512
    __shared__ float dd[DM];
    dd[j] = d_deta[(size_t)b*DM + j];
    __syncthreads();
    const float* wo = d_WOM + (size_t)j*DM;
    float acc = bO[j];
    #pragma unroll 8
    for (int i = 0; i < DM; i++) acc += dd[i]*wo[i];
    out[(size_t)b*DM + j] = x_pre[(size_t)b*DM + j] + acc;
}

extern "C" void kernel_launch(void* const* d_in, const int* in_sizes, int n_in,
                              void* d_out, int out_size) {
    const float* memory = (const float*)d_in[0];
    const float* x_pre  = (const float*)d_in[1];
    const float* aux    = (const float*)d_in[2];
    const float* pos    = (const float*)d_in[3];
    const float* Wq  = (const float*)d_in[4];
    const float* bq  = (const float*)d_in[5];
    const float* Wk  = (const float*)d_in[6];
    const float* bk  = (const float*)d_in[7];
    const float* Wv  = (const float*)d_in[8];
    const float* bv  = (const float*)d_in[9];
    const float* Wqa = (const float*)d_in[10];
    const float* bqa = (const float*)d_in[11];
    const float* Wka = (const float*)d_in[12];
    const float* bka = (const float*)d_in[13];
    const float* Wqp = (const float*)d_in[14];
    const float* bqp = (const float*)d_in[15];
    const float* Wkp = (const float*)d_in[16];
    const float* bkp = (const float*)d_in[17];
    const float* W_ih = (const float*)d_in[18];
    const float* W_hh = (const float*)d_in[19];
    const float* b_ih = (const float*)d_in[20];
    const float* b_hh = (const float*)d_in[21];
    const float* WO = (const float*)d_in[22];
    const float* bO = (const float*)d_in[23];
    const float* w   = (const float*)d_in[24];
    const float* w_a = (const float*)d_in[25];
    const float* w_p = (const float*)d_in[26];
    const int* G = (const int*)d_in[27];
    float* out = (float*)d_out;

    int S  = in_sizes[2] / (BDIM*DA);   // 6144
    int Wn = S - MDIM + 1;              // 6113

    mask_kernel<<<1024, 256>>>(Wq, Wk, Wv, WO, G);
    qv_kernel<<<BDIM*HDIM*MDIM, 64>>>(memory, x_pre, bq, S);
    proj_mma_kernel<DM, DK, 0, 192, 2><<<dim3(S/96, HDIM, BDIM), 192>>>(memory, x_pre, nullptr, bk, S, Wn);
    band_mma_kernel<<<dim3((Wn + 63)/64, HDIM, BDIM), 128>>>(S, Wn);
    qa_kernel<<<BDIM*HDIM, 32>>>(aux, Wqa, bqa, S);
    proj_mma_kernel<DA, DAH, 1, 128, 1><<<dim3(S/128, HDIM, BDIM), 128>>>(aux, nullptr, Wka, bka, S, Wn);
    qp_kernel<<<BDIM*HDIM, 32>>>(pos, Wqp, bqp, S);
    proj_mma_kernel<DP, DPH, 2, 128, 1><<<dim3(S/128, HDIM, BDIM), 128>>>(pos, nullptr, Wkp, bkp, S, Wn);
    softmax_kernel<<<BDIM*HDIM, 256>>>(w, w_a, w_p, S, Wn);
    xbar_kernel<<<dim3((Wn - 1 + 63)/64, BDIM), 256>>>(memory, S, Wn);
    gi_kernel<<<dim3(31, BDIM), 192>>>(memory, W_ih, b_ih, S);
    gru_kernel<<<BDIM, 192>>>(W_hh, b_hh);
    deta_kernel<<<BDIM*HDIM, 64>>>(bv);
    out_kernel<<<BDIM, 512>>>(x_pre, bO, out);
}

// round 5
// speedup vs baseline: 1.5508x; 1.5508x over previous
#include <cuda_runtime.h>
#include <math.h>
#include <stdint.h>
#include <stddef.h>

// fixed problem shapes
#define BDIM 8
#define HDIM 8
#define DM 512
#define DA 256
#define DP 128
#define MDIM 32
#define DK 64
#define DAH 32
#define DPH 16
#define SDIM 6144

// ---------------- device scratch ----------------
__device__ float d_WqM[HDIM*DK*DM];
__device__ float d_WkM[HDIM*DK*DM];
__device__ float d_WvM[HDIM*DK*DM];
__device__ float d_WOM[DM*DM];
__device__ float d_Kn[(size_t)BDIM*HDIM*SDIM*DK];   // ~100 MB
__device__ float d_Qv[BDIM*HDIM*MDIM*DK];
__device__ float d_QA[BDIM*HDIM*DAH];
__device__ float d_QP[BDIM*HDIM*DPH];
__device__ float d_tn[BDIM*HDIM*SDIM];
__device__ float d_dot2[BDIM*HDIM*SDIM];
__device__ float d_dot3[BDIM*HDIM*SDIM];
__device__ float d_attn[BDIM*HDIM*SDIM];
__device__ float d_alast[BDIM*HDIM];
__device__ float d_xbar[BDIM*HDIM*DM];
__device__ float d_gi[BDIM*31*192];
__device__ float d_res[BDIM*DK];
__device__ float d_deta[BDIM*DM];

__device__ __forceinline__ void mma_tf32(float* c, const uint32_t* a, uint32_t b0, uint32_t b1) {
    asm volatile("mma.sync.aligned.m16n8k8.row.col.f32.tf32.tf32.f32 "
        "{%0,%1,%2,%3}, {%4,%5,%6,%7}, {%8,%9}, {%0,%1,%2,%3};\n"
        : "+f"(c[0]), "+f"(c[1]), "+f"(c[2]), "+f"(c[3])
        : "r"(a[0]), "r"(a[1]), "r"(a[2]), "r"(a[3]), "r"(b0), "r"(b1));
}

__device__ __forceinline__ void cpa16(uint32_t saddr, const void* g) {
    asm volatile("cp.async.cg.shared.global [%0], [%1], 16;" :: "r"(saddr), "l"(g));
}
__device__ __forceinline__ void cpa_commit() { asm volatile("cp.async.commit_group;"); }
__device__ __forceinline__ void cpa_wait0() { asm volatile("cp.async.wait_group 0;" ::: "memory"); }

// ---------------- masked weights + zero xbar ----------------
__global__ void mask_kernel(const float* __restrict__ Wq, const float* __restrict__ Wk,
                            const float* __restrict__ Wv, const float* __restrict__ WO,
                            const int* __restrict__ G) {
    int i = blockIdx.x*256 + threadIdx.x;
    const int NW = HDIM*DK*DM;
    if (i < NW) {
        int d = i & 511;
        int c = (i >> 9) & 63;
        float g = (float)G[c*64 + (d & 63)];
        d_WqM[i] = Wq[i]*g;
        d_WkM[i] = Wk[i]*g;
        d_WvM[i] = Wv[i]*g;
    }
    if (i < DM*DM) {
        int j = i & 511, r = i >> 9;
        d_WOM[i] = WO[i]*(float)G[(r & 63)*64 + (j & 63)];
    }
    if (i < BDIM*HDIM*DM) d_xbar[i] = 0.f;
}

// ---------------- Qv: last M rows, masked proj + l2norm (fp32, tiny) ----------------
__global__ void qv_kernel(const float* __restrict__ memory, const float* __restrict__ x_pre,
                          const float* __restrict__ bq, int S) {
    int m = blockIdx.x & 31, h = (blockIdx.x >> 5) & 7, b = blockIdx.x >> 8;
    __shared__ float xs[DM];
    __shared__ float wp[2];
    int s = S - MDIM + m;
    const float* row = (s < S-1) ? memory + ((size_t)b*(S-1) + s)*DM : x_pre + (size_t)b*DM;
    for (int i = threadIdx.x; i < DM; i += 64) xs[i] = row[i];
    __syncthreads();
    int c = threadIdx.x;
    const float* wr = d_WqM + ((size_t)h*DK + c)*DM;
    float acc = bq[h*DK + c];
    #pragma unroll 8
    for (int d = 0; d < DM; d++) acc += xs[d]*wr[d];
    float v = acc*acc;
    for (int o = 16; o; o >>= 1) v += __shfl_xor_sync(0xffffffffu, v, o);
    if ((c & 31) == 0) wp[c >> 5] = v;
    __syncthreads();
    float inv = 1.f / fmaxf(sqrtf(wp[0] + wp[1]), 1e-12f);
    d_Qv[(((size_t)b*HDIM + h)*MDIM + m)*DK + c] = acc*inv;
}

// ---------------- tensor-core projection (tf32 mma, cp.async single-stage) ----------------
// MODE 0: kproj  (x = [memory; x_pre]; W = d_WkM; out = normalized rows -> d_Kn)
// MODE 1: aux    (epilogue: dot with d_QA -> d_dot2)
// MODE 2: pos    (epilogue: dot with d_QP -> d_dot3)
template<int DIN, int DOUT, int MODE, int NW_N>
__global__ void __launch_bounds__(256)
proj_mma_kernel(const float* __restrict__ src0, const float* __restrict__ x_pre,
                const float* __restrict__ W, const float* __restrict__ bias,
                int S, int Wn) {
    constexpr int NW_M = 8/NW_N;
    constexpr int TM   = NW_M*32;
    constexpr int WT_N = DOUT/NW_N;
    constexpr int NFN  = WT_N/8;
    constexpr int NCH  = DIN/32;

    __shared__ uint32_t Xs[TM*36];
    __shared__ uint32_t Wss[DOUT*36];
    __shared__ float bs_s[DOUT];
    __shared__ float qs_s[DOUT];
    __shared__ float red_s[TM*2];

    int tid = threadIdx.x;
    int lane = tid & 31, wid = tid >> 5;
    int g = lane >> 2, tig = lane & 3;
    int warp_n = wid % NW_N, warp_m = wid / NW_N;
    int rb = warp_m*32, cb = warp_n*WT_N;
    int s0 = blockIdx.x*TM, h = blockIdx.y, b = blockIdx.z;
    int bh = b*HDIM + h;

    uint32_t xB = (uint32_t)__cvta_generic_to_shared(Xs);
    uint32_t wB = (uint32_t)__cvta_generic_to_shared(Wss);

    for (int i = tid; i < DOUT; i += 256) {
        bs_s[i] = bias[h*DOUT + i];
        if (MODE == 1) qs_s[i] = d_QA[(size_t)bh*DAH + i];
        if (MODE == 2) qs_s[i] = d_QP[(size_t)bh*DPH + i];
    }

    float acc[2][NFN][4];
    #pragma unroll
    for (int mi = 0; mi < 2; mi++)
        #pragma unroll
        for (int ni = 0; ni < NFN; ni++)
            #pragma unroll
            for (int q = 0; q < 4; q++) acc[mi][ni][q] = 0.f;

    for (int ch = 0; ch < NCH; ch++) {
        int d0 = ch*32;
        // stage X tile (TM x 32) via cp.async
        #pragma unroll
        for (int it = 0; it < TM*8/256; it++) {
            int e = it*256 + tid;
            int row = e >> 3, c4 = (e & 7)*4;
            int s = s0 + row;
            const float* rp;
            if (MODE == 0)
                rp = (s < S-1) ? src0 + ((size_t)b*(S-1) + s)*DIN : x_pre + (size_t)b*DIN;
            else
                rp = src0 + ((size_t)b*S + s)*DIN;
            cpa16(xB + (row*36 + c4)*4, rp + d0 + c4);
        }
        // stage W tile (DOUT x 32)
        for (int e = tid; e < DOUT*8; e += 256) {
            int rr = e >> 3, c4 = (e & 7)*4;
            const float* wp;
            if (MODE == 0) wp = d_WkM + ((size_t)(h*DOUT + rr))*DIN + d0 + c4;
            else           wp = W + ((size_t)(h*DOUT + rr))*DIN + d0 + c4;
            cpa16(wB + (rr*36 + c4)*4, wp);
        }
        cpa_commit();
        cpa_wait0();
        __syncthreads();
        #pragma unroll
        for (int ks = 0; ks < 4; ks++) {
            int k0 = ks*8;
            uint32_t a[2][4];
            #pragma unroll
            for (int mi = 0; mi < 2; mi++) {
                int r = rb + mi*16 + g;
                a[mi][0] = Xs[r*36 + k0 + tig];
                a[mi][1] = Xs[(r+8)*36 + k0 + tig];
                a[mi][2] = Xs[r*36 + k0 + tig + 4];
                a[mi][3] = Xs[(r+8)*36 + k0 + tig + 4];
            }
            #pragma unroll
            for (int ni = 0; ni < NFN; ni++) {
                int cn = cb + ni*8 + g;
                uint32_t b0 = Wss[cn*36 + k0 + tig];
                uint32_t b1 = Wss[cn*36 + k0 + tig + 4];
                #pragma unroll
                for (int mi = 0; mi < 2; mi++) mma_tf32(acc[mi][ni], a[mi], b0, b1);
            }
        }
        __syncthreads();
    }

    // ---- epilogue: bias + per-row l2 norm ----
    float sl[2] = {0.f, 0.f}, sh[2] = {0.f, 0.f};
    #pragma unroll
    for (int mi = 0; mi < 2; mi++)
        #pragma unroll
        for (int ni = 0; ni < NFN; ni++) {
            int c0 = cb + ni*8 + 2*tig, c1 = c0 + 1;
            acc[mi][ni][0] += bs_s[c0];
            acc[mi][ni][1] += bs_s[c1];
            acc[mi][ni][2] += bs_s[c0];
            acc[mi][ni][3] += bs_s[c1];
            sl[mi] += acc[mi][ni][0]*acc[mi][ni][0] + acc[mi][ni][1]*acc[mi][ni][1];
            sh[mi] += acc[mi][ni][2]*acc[mi][ni][2] + acc[mi][ni][3]*acc[mi][ni][3];
        }
    #pragma unroll
    for (int mi = 0; mi < 2; mi++) {
        sl[mi] += __shfl_xor_sync(0xffffffffu, sl[mi], 1);
        sl[mi] += __shfl_xor_sync(0xffffffffu, sl[mi], 2);
        sh[mi] += __shfl_xor_sync(0xffffffffu, sh[mi], 1);
        sh[mi] += __shfl_xor_sync(0xffffffffu, sh[mi], 2);
    }
    if (NW_N == 2) {
        if (tig == 0) {
            #pragma unroll
            for (int mi = 0; mi < 2; mi++) {
                int rl = rb + mi*16 + g;
                red_s[rl*2 + warp_n] = sl[mi];
                red_s[(rl+8)*2 + warp_n] = sh[mi];
            }
        }
        __syncthreads();
        #pragma unroll
        for (int mi = 0; mi < 2; mi++) {
            int rl = rb + mi*16 + g;
            sl[mi] = red_s[rl*2] + red_s[rl*2+1];
            sh[mi] = red_s[(rl+8)*2] + red_s[(rl+8)*2+1];
        }
    }
    float il[2], ih[2];
    #pragma unroll
    for (int mi = 0; mi < 2; mi++) {
        il[mi] = 1.f / fmaxf(sqrtf(sl[mi]), 1e-12f);
        ih[mi] = 1.f / fmaxf(sqrtf(sh[mi]), 1e-12f);
    }

    if (MODE == 0) {
        #pragma unroll
        for (int mi = 0; mi < 2; mi++) {
            int rl = rb + mi*16 + g;
            size_t base_l = ((size_t)bh*S + s0 + rl)*DK;
            size_t base_h = ((size_t)bh*S + s0 + rl + 8)*DK;
            #pragma unroll
            for (int ni = 0; ni < NFN; ni++) {
                int c0 = cb + ni*8 + 2*tig;
                float2 v0 = make_float2(acc[mi][ni][0]*il[mi], acc[mi][ni][1]*il[mi]);
                float2 v1 = make_float2(acc[mi][ni][2]*ih[mi], acc[mi][ni][3]*ih[mi]);
                *(float2*)&d_Kn[base_l + c0] = v0;
                *(float2*)&d_Kn[base_h + c0] = v1;
            }
        }
    } else {
        float* dst = (MODE == 1) ? d_dot2 : d_dot3;
        #pragma unroll
        for (int mi = 0; mi < 2; mi++) {
            float dl = 0.f, dh = 0.f;
            #pragma unroll
            for (int ni = 0; ni < NFN; ni++) {
                int c0 = cb + ni*8 + 2*tig, c1 = c0 + 1;
                dl += acc[mi][ni][0]*qs_s[c0] + acc[mi][ni][1]*qs_s[c1];
                dh += acc[mi][ni][2]*qs_s[c0] + acc[mi][ni][3]*qs_s[c1];
            }
            dl += __shfl_xor_sync(0xffffffffu, dl, 1);
            dl += __shfl_xor_sync(0xffffffffu, dl, 2);
            dh += __shfl_xor_sync(0xffffffffu, dh, 1);
            dh += __shfl_xor_sync(0xffffffffu, dh, 2);
            if (tig == 0) {
                int rl = rb + mi*16 + g;
                int wl = s0 + rl - 31;
                int wh = wl + 8;
                if (wl >= 0 && wl < Wn) dst[(size_t)bh*S + wl] = dl*il[mi];
                if (wh >= 0 && wh < Wn) dst[(size_t)bh*S + wh] = dh*ih[mi];
            }
        }
    }
}

// ---------------- banded Qv . Kn -> tn  (tf32 mma version) ----------------
__global__ void __launch_bounds__(128) band_mma_kernel(int S, int Wn) {
    __shared__ uint32_t Qs[32*68];
    __shared__ uint32_t Ks[96*68];
    __shared__ float Ps[32*100];
    int tid = threadIdx.x;
    int lane = tid & 31, wid = tid >> 5;
    int g = lane >> 2, tig = lane & 3;
    int w0 = blockIdx.x*64, h = blockIdx.y, b = blockIdx.z;
    int bh = b*HDIM + h;

    uint32_t qB = (uint32_t)__cvta_generic_to_shared(Qs);
    uint32_t kB = (uint32_t)__cvta_generic_to_shared(Ks);

    for (int e = tid; e < 96*16; e += 128) {
        int r = e >> 4, c4 = (e & 15)*4;
        int s = w0 + r;
        uint32_t sa = kB + (r*68 + c4)*4;
        if (s < S) cpa16(sa, d_Kn + ((size_t)bh*S + s)*DK + c4);
        else {
            *(float4*)((char*)Ks + (size_t)(r*68 + c4)*4) = make_float4(0.f,0.f,0.f,0.f);
        }
    }
    for (int e = tid; e < 32*16; e += 128) {
        int r = e >> 4, c4 = (e & 15)*4;
        cpa16(qB + (r*68 + c4)*4, d_Qv + ((size_t)bh*MDIM + r)*DK + c4);
    }
    cpa_commit();
    cpa_wait0();
    __syncthreads();

    float acc[2][3][4];
    #pragma unroll
    for (int mi = 0; mi < 2; mi++)
        #pragma unroll
        for (int ni = 0; ni < 3; ni++)
            #pragma unroll
            for (int q = 0; q < 4; q++) acc[mi][ni][q] = 0.f;
    int nb = wid*24;
    #pragma unroll
    for (int ks = 0; ks < 8; ks++) {
        int k0 = ks*8;
        uint32_t a[2][4];
        #pragma unroll
        for (int mi = 0; mi < 2; mi++) {
            int r = mi*16 + g;
            a[mi][0] = Qs[r*68 + k0 + tig];
            a[mi][1] = Qs[(r+8)*68 + k0 + tig];
            a[mi][2] = Qs[r*68 + k0 + tig + 4];
            a[mi][3] = Qs[(r+8)*68 + k0 + tig + 4];
        }
        #pragma unroll
        for (int ni = 0; ni < 3; ni++) {
            int cn = nb + ni*8 + g;
            uint32_t b0 = Ks[cn*68 + k0 + tig];
            uint32_t b1 = Ks[cn*68 + k0 + tig + 4];
            #pragma unroll
            for (int mi = 0; mi < 2; mi++) mma_tf32(acc[mi][ni], a[mi], b0, b1);
        }
    }
    #pragma unroll
    for (int mi = 0; mi < 2; mi++)
        #pragma unroll
        for (int ni = 0; ni < 3; ni++) {
            int c0 = nb + ni*8 + 2*tig;
            int r = mi*16 + g;
            Ps[r*100 + c0]     = acc[mi][ni][0];
            Ps[r*100 + c0 + 1] = acc[mi][ni][1];
            Ps[(r+8)*100 + c0]     = acc[mi][ni][2];
            Ps[(r+8)*100 + c0 + 1] = acc[mi][ni][3];
        }
    __syncthreads();
    if (tid < 64) {
        int w = w0 + tid;
        if (w < Wn) {
            float s = 0.f;
            #pragma unroll
            for (int m = 0; m < 32; m++) s += Ps[m*100 + tid + m];
            d_tn[(size_t)bh*S + w] = s*(1.f/32.f);
        }
    }
}

// ---------------- QA / QP (last-row queries, fp32) ----------------
__global__ void qa_kernel(const float* __restrict__ aux, const float* __restrict__ Wqa,
                          const float* __restrict__ bqa, int S) {
    int h = blockIdx.x & 7, b = blockIdx.x >> 3;
    int c = threadIdx.x;  // 32
    const float* ar = aux + ((size_t)b*S + (S-1))*DA;
    const float* wr = Wqa + ((size_t)h*DAH + c)*DA;
    float acc = bqa[h*DAH + c];
    #pragma unroll 4
    for (int d = 0; d < DA; d++) acc += ar[d]*wr[d];
    float v = acc*acc;
    for (int o = 16; o; o >>= 1) v += __shfl_xor_sync(0xffffffffu, v, o);
    float inv = 1.f / fmaxf(sqrtf(v), 1e-12f);
    d_QA[((size_t)b*HDIM + h)*DAH + c] = acc*inv;
}

__global__ void qp_kernel(const float* __restrict__ pos, const float* __restrict__ Wqp,
                          const float* __restrict__ bqp, int S) {
    int h = blockIdx.x & 7, b = blockIdx.x >> 3;
    int lane = threadIdx.x;   // 32
    int c = lane & 15;
    const float* pr = pos + ((size_t)b*S + (S-1))*DP;
    const float* wr = Wqp + ((size_t)h*DPH + c)*DP;
    float acc = bqp[h*DPH + c];
    #pragma unroll 4
    for (int d = 0; d < DP; d++) acc += pr[d]*wr[d];
    float v = acc*acc;
    for (int o = 8; o; o >>= 1) v += __shfl_xor_sync(0xffffffffu, v, o);
    float inv = 1.f / fmaxf(sqrtf(v), 1e-12f);
    if (lane < 16) d_QP[((size_t)b*HDIM + h)*DPH + c] = acc*inv;
}

// ---------------- softmax over Wn ----------------
__global__ void softmax_kernel(const float* __restrict__ w1, const float* __restrict__ w2,
                               const float* __restrict__ w3, int S, int Wn) {
    int bh = blockIdx.x, t = threadIdx.x;   // 256
    __shared__ float red[8];
    __shared__ float sval;
    float c1 = w1[0], c2 = w2[0], c3 = w3[0];
    size_t base = (size_t)bh*S;
    float mx = -1e30f;
    for (int i = t; i < Wn; i += 256) {
        float l = c1*d_tn[base+i] + c2*d_dot2[base+i] + c3*d_dot3[base+i];
        d_attn[base+i] = l;
        mx = fmaxf(mx, l);
    }
    for (int o = 16; o; o >>= 1) mx = fmaxf(mx, __shfl_xor_sync(0xffffffffu, mx, o));
    if ((t & 31) == 0) red[t >> 5] = mx;
    __syncthreads();
    if (t == 0) { float m = red[0]; for (int i = 1; i < 8; i++) m = fmaxf(m, red[i]); sval = m; }
    __syncthreads();
    float MX = sval, sum = 0.f;
    for (int i = t; i < Wn; i += 256) {
        float e = __expf(d_attn[base+i] - MX);
        d_attn[base+i] = e;
        sum += e;
    }
    for (int o = 16; o; o >>= 1) sum += __shfl_xor_sync(0xffffffffu, sum, o);
    __syncthreads();
    if ((t & 31) == 0) red[t >> 5] = sum;
    __syncthreads();
    if (t == 0) { float m = 0.f; for (int i = 0; i < 8; i++) m += red[i]; sval = m; }
    __syncthreads();
    float inv = 1.f / sval;
    for (int i = t; i < Wn; i += 256) {
        float a = d_attn[base+i]*inv;
        d_attn[base+i] = a;
        if (i == Wn-1) d_alast[bh] = a;
    }
}

// ---------------- xbar: attn-weighted row sums of x ----------------
__global__ void xbar_kernel(const float* __restrict__ memory, int S, int Wn) {
    __shared__ float a_s[8][64];
    int t = threadIdx.x;                 // 256
    int w0 = blockIdx.x*64, b = blockIdx.y;
    for (int i = t; i < 512; i += 256) {
        int hh = i >> 6, j = i & 63;
        int w = w0 + j;
        a_s[hh][j] = (w < Wn-1) ? d_attn[((size_t)b*HDIM + hh)*S + w] : 0.f;
    }
    __syncthreads();
    float acc[8][2];
    #pragma unroll
    for (int h = 0; h < 8; h++) { acc[h][0] = 0.f; acc[h][1] = 0.f; }
    int nrow = Wn - 1 - w0; if (nrow > 64) nrow = 64;
    for (int j = 0; j < nrow; j++) {
        size_t sr = (size_t)b*(S-1) + (31 + w0 + j);
        float x0 = memory[sr*DM + t];
        float x1 = memory[sr*DM + 256 + t];
        #pragma unroll
        for (int h = 0; h < 8; h++) {
            float a = a_s[h][j];
            acc[h][0] += a*x0;
            acc[h][1] += a*x1;
        }
    }
    #pragma unroll
    for (int h = 0; h < 8; h++) {
        atomicAdd(&d_xbar[((size_t)b*HDIM + h)*DM + t], acc[h][0]);
        atomicAdd(&d_xbar[((size_t)b*HDIM + h)*DM + 256 + t], acc[h][1]);
    }
}

// ---------------- GRU ----------------
__global__ void gi_kernel(const float* __restrict__ memory, const float* __restrict__ W_ih,
                          const float* __restrict__ b_ih, int S) {
    int tt = blockIdx.x, b = blockIdx.y;
    __shared__ float xs[DM];
    int s = S - MDIM + tt;               // always memory row (tt <= 30)
    const float* row = memory + ((size_t)b*(S-1) + s)*DM;
    for (int i = threadIdx.x; i < DM; i += 192) xs[i] = row[i];
    __syncthreads();
    int j = threadIdx.x;
    const float* wr = W_ih + (size_t)j*DM;
    float acc = b_ih[j];
    #pragma unroll 8
    for (int d = 0; d < DM; d++) acc += xs[d]*wr[d];
    d_gi[((size_t)b*31 + tt)*192 + j] = acc;
}

__global__ void gru_kernel(const float* __restrict__ W_hh, const float* __restrict__ b_hh) {
    int b = blockIdx.x, j = threadIdx.x;  // 192
    __shared__ float hs[DK];
    __shared__ float gh_s[192];
    if (j < DK) hs[j] = 0.f;
    __syncthreads();
    float bh = b_hh[j];
    const float* wr = W_hh + (size_t)j*DK;
    for (int t = 0; t < 31; t++) {
        float gh = bh;
        #pragma unroll 8
        for (int k2 = 0; k2 < DK; k2++) gh += hs[k2]*wr[k2];
        gh_s[j] = gh;
        __syncthreads();
        float hn = 0.f;
        if (j < DK) {
            const float* gi = d_gi + ((size_t)b*31 + t)*192;
            float r = 1.f/(1.f + __expf(-(gi[j] + gh_s[j])));
            float z = 1.f/(1.f + __expf(-(gi[64 + j] + gh_s[64 + j])));
            float n = tanhf(gi[128 + j] + r*gh_s[128 + j]);
            hn = (1.f - z)*n + z*hs[j];
        }
        __syncthreads();
        if (j < DK) hs[j] = hn;
        __syncthreads();
    }
    if (j < DK) d_res[b*DK + j] = hs[j];
}

// ---------------- deta = xbar @ WvM^T + bv*(1-alast) + alast*res ----------------
__global__ void deta_kernel(const float* __restrict__ bv) {
    int bh = blockIdx.x;
    int b = bh >> 3, h = bh & 7;
    int c = threadIdx.x;                 // 64
    __shared__ float xb[DM];
    for (int i = c; i < DM; i += 64) xb[i] = d_xbar[(size_t)bh*DM + i];
    __syncthreads();
    const float* wv = d_WvM + ((size_t)h*DK + c)*DM;
    float acc = 0.f;
    #pragma unroll 8
    for (int d = 0; d < DM; d++) acc += xb[d]*wv[d];
    float al = d_alast[bh];
    d_deta[(size_t)b*DM + h*DK + c] = acc + bv[h*DK + c]*(1.f - al) + al*d_res[b*DK + c];
}

// ---------------- out = x_pre + deta @ WOM^T + bO ----------------
__global__ void out_kernel(const float* __restrict__ x_pre, const float* __restrict__ bO,
                           float* __restrict__ out) {
    int b = blockIdx.x, j = threadIdx.x;  // 512
    __shared__ float dd[DM];
    dd[j] = d_deta[(size_t)b*DM + j];
    __syncthreads();
    const float* wo = d_WOM + (size_t)j*DM;
    float acc = bO[j];
    #pragma unroll 8
    for (int i = 0; i < DM; i++) acc += dd[i]*wo[i];
    out[(size_t)b*DM + j] = x_pre[(size_t)b*DM + j] + acc;
}

extern "C" void kernel_launch(void* const* d_in, const int* in_sizes, int n_in,
                              void* d_out, int out_size) {
    const float* memory = (const float*)d_in[0];
    const float* x_pre  = (const float*)d_in[1];
    const float* aux    = (const float*)d_in[2];
    const float* pos    = (const float*)d_in[3];
    const float* Wq  = (const float*)d_in[4];
    const float* bq  = (const float*)d_in[5];
    const float* Wk  = (const float*)d_in[6];
    const float* bk  = (const float*)d_in[7];
    const float* Wv  = (const float*)d_in[8];
    const float* bv  = (const float*)d_in[9];
    const float* Wqa = (const float*)d_in[10];
    const float* bqa = (const float*)d_in[11];
    const float* Wka = (const float*)d_in[12];
    const float* bka = (const float*)d_in[13];
    const float* Wqp = (const float*)d_in[14];
    const float* bqp = (const float*)d_in[15];
    const float* Wkp = (const float*)d_in[16];
    const float* bkp = (const float*)d_in[17];
    const float* W_ih = (const float*)d_in[18];
    const float* W_hh = (const float*)d_in[19];
    const float* b_ih = (const float*)d_in[20];
    const float* b_hh = (const float*)d_in[21];
    const float* WO = (const float*)d_in[22];
    const float* bO = (const float*)d_in[23];
    const float* w   = (const float*)d_in[24];
    const float* w_a = (const float*)d_in[25];
    const float* w_p = (const float*)d_in[26];
    const int* G = (const int*)d_in[27];
    float* out = (float*)d_out;

    int S  = in_sizes[2] / (BDIM*DA);   // 6144
    int Wn = S - MDIM + 1;              // 6113

    mask_kernel<<<1024, 256>>>(Wq, Wk, Wv, WO, G);
    qv_kernel<<<BDIM*HDIM*MDIM, 64>>>(memory, x_pre, bq, S);
    proj_mma_kernel<DM, DK, 0, 2><<<dim3(S/128, HDIM, BDIM), 256>>>(memory, x_pre, nullptr, bk, S, Wn);
    band_mma_kernel<<<dim3((Wn + 63)/64, HDIM, BDIM), 128>>>(S, Wn);
    qa_kernel<<<BDIM*HDIM, 32>>>(aux, Wqa, bqa, S);
    proj_mma_kernel<DA, DAH, 1, 1><<<dim3(S/256, HDIM, BDIM), 256>>>(aux, nullptr, Wka, bka, S, Wn);
    qp_kernel<<<BDIM*HDIM, 32>>>(pos, Wqp, bqp, S);
    proj_mma_kernel<DP, DPH, 2, 1><<<dim3(S/256, HDIM, BDIM), 256>>>(pos, nullptr, Wkp, bkp, S, Wn);
    softmax_kernel<<<BDIM*HDIM, 256>>>(w, w_a, w_p, S, Wn);
    xbar_kernel<<<dim3((Wn - 1 + 63)/64, BDIM), 256>>>(memory, S, Wn);
    gi_kernel<<<dim3(31, BDIM), 192>>>(memory, W_ih, b_ih, S);
    gru_kernel<<<BDIM, 192>>>(W_hh, b_hh);
    deta_kernel<<<BDIM*HDIM, 64>>>(bv);
    out_kernel<<<BDIM, 512>>>(x_pre, bO, out);
}